// round 11
// baseline (speedup 1.0000x reference)
#include <cuda_runtime.h>
#include <cuda_bf16.h>
#include <cstdint>
#include <math.h>

#define BATCH   16384
#define FK      64
#define VISD    2048
#define HID     512
#define NUSERS  1000000
#define VOCAB   (NUSERS + 24 + 2 + 8 + 40)

// Scratch (allocation-free rule: __device__ globals)
__device__ __nv_bfloat16 g_xh [BATCH * 384];
__device__ __nv_bfloat16 g_w1h[HID * 384];
__device__ __nv_bfloat16 g_w2h[HID * HID];
__device__ float         g_fm [BATCH * 2];

// ---------------------------------------------------------------------------
// helpers (portable PTX only — harness targets compute_103, no 'a' features)
// ---------------------------------------------------------------------------
__device__ __forceinline__ uint32_t smem_u32(const void* p) {
    uint32_t a;
    asm("{ .reg .u64 t; cvta.to.shared.u64 t, %1; cvt.u32.u64 %0, t; }"
        : "=r"(a) : "l"(p));
    return a;
}
__device__ __forceinline__ void cp16(uint32_t s, const void* g) {
    asm volatile("cp.async.cg.shared.global [%0], [%1], 16;" :: "r"(s), "l"(g));
}
__device__ __forceinline__ void cp_commit() {
    asm volatile("cp.async.commit_group;" ::: "memory");
}
template<int N> __device__ __forceinline__ void cp_wait() {
    asm volatile("cp.async.wait_group %0;" :: "n"(N) : "memory");
}
__device__ __forceinline__ void ldsm4(uint32_t r[4], uint32_t addr) {
    asm volatile("ldmatrix.sync.aligned.m8n8.x4.shared.b16 {%0,%1,%2,%3}, [%4];"
        : "=r"(r[0]), "=r"(r[1]), "=r"(r[2]), "=r"(r[3]) : "r"(addr));
}
__device__ __forceinline__ void mma_tf32(float d[4], const uint32_t a[4],
                                         const uint32_t b[2]) {
    asm volatile(
        "mma.sync.aligned.m16n8k8.row.col.f32.tf32.tf32.f32 "
        "{%0,%1,%2,%3}, {%4,%5,%6,%7}, {%8,%9}, {%0,%1,%2,%3};"
        : "+f"(d[0]), "+f"(d[1]), "+f"(d[2]), "+f"(d[3])
        : "r"(a[0]), "r"(a[1]), "r"(a[2]), "r"(a[3]), "r"(b[0]), "r"(b[1]));
}
__device__ __forceinline__ void mma_bf16(float d[4], const uint32_t a[4],
                                         const uint32_t b[2]) {
    asm volatile(
        "mma.sync.aligned.m16n8k16.row.col.f32.bf16.bf16.f32 "
        "{%0,%1,%2,%3}, {%4,%5,%6,%7}, {%8,%9}, {%0,%1,%2,%3};"
        : "+f"(d[0]), "+f"(d[1]), "+f"(d[2]), "+f"(d[3])
        : "r"(a[0]), "r"(a[1]), "r"(a[2]), "r"(a[3]), "r"(b[0]), "r"(b[1]));
}
__device__ __forceinline__ uint32_t pack_bf16(float lo, float hi) {
    uint32_t r;
    asm("cvt.rn.bf16x2.f32 %0, %1, %2;" : "=r"(r) : "f"(hi), "f"(lo));
    return r;
}

// ---------------------------------------------------------------------------
// Weight conversion: w1, w2 fp32 -> bf16
// ---------------------------------------------------------------------------
__global__ void conv_w_kernel(const float* __restrict__ w1,
                              const float* __restrict__ w2)
{
    const int N1 = HID * 384 / 4;
    int i = blockIdx.x * blockDim.x + threadIdx.x;
    if (i < N1) {
        float4 v = ((const float4*)w1)[i];
        uint2 o = { pack_bf16(v.x, v.y), pack_bf16(v.z, v.w) };
        ((uint2*)g_w1h)[i] = o;
    } else {
        int j = i - N1;
        float4 v = ((const float4*)w2)[j];
        uint2 o = { pack_bf16(v.x, v.y), pack_bf16(v.z, v.w) };
        ((uint2*)g_w2h)[j] = o;
    }
}

// ---------------------------------------------------------------------------
// tf32 GEMM (vis): 64x64 tile, 4-stage cp.async, ldmatrix frags (proven R8).
// ---------------------------------------------------------------------------
__global__ __launch_bounds__(256, 2) void gemm_tf32_vis(
    const float* __restrict__ A,
    const float* __restrict__ W,
    const float* __restrict__ bias,
    __nv_bfloat16* __restrict__ C)
{
    constexpr int BM = 64, BN = 64, BK = 32, S = 4;
    constexpr int LDT = 36;
    constexpr int WM = 2, WN = 4, TN = 2;
    constexpr int ASZ = BM * LDT;
    constexpr int WSZ = BN * LDT;

    extern __shared__ float sm[];
    float* sA = sm;
    float* sW = sm + S * ASZ;
    __shared__ float sbias[BN];

    const int tid = threadIdx.x;
    const int m0  = blockIdx.x * BM;
    const int NC  = VISD / BK;

    if (tid < BN) sbias[tid] = bias[tid];

    const uint32_t sAu = smem_u32(sA);
    const uint32_t sWu = smem_u32(sW);

    auto load_tiles = [&](int c) {
        const int st = c % S;
        const int k0 = c * BK;
        #pragma unroll
        for (int j = 0; j < BM / 32; j++) {
            int i = tid + j * 256;
            int r = i >> 3, sg = i & 7;
            cp16(sAu + (st * ASZ + r * LDT) * 4 + sg * 16,
                 A + (size_t)(m0 + r) * VISD + k0 + sg * 4);
        }
        #pragma unroll
        for (int j = 0; j < BN / 32; j++) {
            int i = tid + j * 256;
            int r = i >> 3, sg = i & 7;
            cp16(sWu + (st * WSZ + r * LDT) * 4 + sg * 16,
                 W + (size_t)r * VISD + k0 + sg * 4);
        }
    };

    const int lane = tid & 31, warp = tid >> 5;
    const int g = lane >> 2, t = lane & 3;
    const int wm = warp % WM, wn = warp / WM;
    const int mbase = wm * 32;
    const int nbase = wn * (BN / WN);

    const uint32_t rowA  = ((lane >> 3) & 1) * 8 + (lane & 7);
    const uint32_t abyte = (lane >> 4) * 16;
    const uint32_t rowB  = ((lane >> 4) << 3) + (lane & 7);
    const uint32_t bbyte = ((lane >> 3) & 1) * 16;

    float acc[2][TN][4] = {};

    load_tiles(0); cp_commit();
    load_tiles(1); cp_commit();
    load_tiles(2); cp_commit();

    for (int c = 0; c < NC; c++) {
        cp_wait<2>();
        __syncthreads();
        if (c + 3 < NC) load_tiles(c + 3);
        cp_commit();

        const uint32_t stA = sAu + (c % S) * ASZ * 4;
        const uint32_t stW = sWu + (c % S) * WSZ * 4;

        #pragma unroll
        for (int ks = 0; ks < 4; ks++) {
            uint32_t af[2][4], bf4[4];
            #pragma unroll
            for (int tm = 0; tm < 2; tm++)
                ldsm4(af[tm], stA + (mbase + tm * 16 + rowA) * (LDT * 4)
                              + ks * 32 + abyte);
            ldsm4(bf4, stW + (nbase + rowB) * (LDT * 4) + ks * 32 + bbyte);
            #pragma unroll
            for (int tm = 0; tm < 2; tm++) {
                mma_tf32(acc[tm][0], af[tm], bf4 + 0);
                mma_tf32(acc[tm][1], af[tm], bf4 + 2);
            }
        }
    }

    #pragma unroll
    for (int tm = 0; tm < 2; tm++) {
        #pragma unroll
        for (int tn = 0; tn < TN; tn++) {
            const int ncol = nbase + tn * 8 + 2 * t;
            const float b0 = sbias[ncol], b1 = sbias[ncol + 1];
            #pragma unroll
            for (int half = 0; half < 2; half++) {
                const int row = m0 + mbase + tm * 16 + g + half * 8;
                float vx = acc[tm][tn][half * 2 + 0] + b0;
                float vy = acc[tm][tn][half * 2 + 1] + b1;
                *(uint32_t*)(g_xh + (size_t)row * 384 + 320 + ncol) =
                    pack_bf16(vx, vy);
            }
        }
    }
}

// ---------------------------------------------------------------------------
// FUSED MLP: h1 = relu(x@w1^T+b1) -> smem; h2 = relu(h1@w2^T+b2) in regs;
// logits = h2 . w3^T; softmax -> out. One CTA owns 64 rows end-to-end.
// 256 threads (8 warps: 2 m-blocks x 4 n-blocks), 3-stage cp.async.
// ---------------------------------------------------------------------------
__global__ __launch_bounds__(256, 2) void fused_mlp(
    const __nv_bfloat16* __restrict__ X,
    const __nv_bfloat16* __restrict__ W1,
    const float* __restrict__ b1,
    const __nv_bfloat16* __restrict__ W2,
    const float* __restrict__ b2,
    const float* __restrict__ w3,
    const float* __restrict__ b3,
    float* __restrict__ out)
{
    constexpr int BM = 64, BK = 32, S = 3;
    constexpr int LDW = 20;                  // stage words per row (16+4 pad)
    constexpr int LDH = 260;                 // h1 words per row (256+4 pad)
    constexpr int XSZ = BM * LDW;            // 1280 words per x stage
    constexpr int WSZ = 128 * LDW;           // 2560 words per W stage

    extern __shared__ uint32_t dsm[];
    uint32_t* sX = dsm;                      // [S][XSZ]  (phase1 only)
    uint32_t* sW = dsm + S * XSZ;            // [S][WSZ]
    uint32_t* sH = dsm + S * XSZ + S * WSZ;  // [64][LDH] h1 tile
    // phase-2 aliases into the (then unused) sX region:
    float* sb2  = (float*)sX;                // 512 floats
    float* sw3  = sb2 + 512;                 // 1024 floats
    float* sred = sw3 + 1024;                // 64 rows x 4 wn x 2

    const int tid = threadIdx.x;
    const int m0  = blockIdx.x * BM;

    const uint32_t sXu = smem_u32(sX);
    const uint32_t sWu = smem_u32(sW);
    const uint32_t sHu = smem_u32(sH);

    const int lane = tid & 31, warp = tid >> 5;
    const int g = lane >> 2, t = lane & 3;
    const int wm = warp & 1;                 // m block (2 x 32 rows)
    const int wn = warp >> 1;                // n block (4 x 32 cols)
    const int mbase = wm * 32;
    const int nbase = wn * 32;
    const uint32_t rowA  = ((lane >> 3) & 1) * 8 + (lane & 7);
    const uint32_t abyte = (lane >> 4) * 16;
    const uint32_t rowB  = ((lane >> 4) << 3) + (lane & 7);
    const uint32_t bbyte = ((lane >> 3) & 1) * 16;

    auto loadX = [&](int c) {                // 64 rows x 4 x 16B = 1/thread
        int st = c % S, k0 = c * BK;
        int r = tid >> 2, sg = tid & 3;
        cp16(sXu + (st * XSZ + r * LDW + sg * 4) * 4,
             X + (size_t)(m0 + r) * 384 + k0 + sg * 8);
    };
    auto loadW = [&](const __nv_bfloat16* Wp, int ldw, int n0, int c) {
        int st = c % S, k0 = c * BK;
        #pragma unroll
        for (int j = 0; j < 2; j++) {        // 128 rows x 4 x 16B = 2/thread
            int i = tid + j * 256;
            int r = i >> 2, sg = i & 3;
            cp16(sWu + (st * WSZ + r * LDW + sg * 4) * 4,
                 Wp + (size_t)(n0 + r) * ldw + k0 + sg * 8);
        }
    };

    // ============ PHASE 1: h1 n-tiles (4 x 128 cols, K=384) -> smem ========
    for (int nt = 0; nt < 4; nt++) {
        const int n0 = nt * 128;
        float acc[2][4][4] = {};

        loadX(0); loadW(W1, 384, n0, 0); cp_commit();
        loadX(1); loadW(W1, 384, n0, 1); cp_commit();

        for (int c = 0; c < 12; c++) {
            cp_wait<1>();
            __syncthreads();
            if (c + 2 < 12) { loadX(c + 2); loadW(W1, 384, n0, c + 2); }
            cp_commit();

            const uint32_t stX = sXu + (c % S) * XSZ * 4;
            const uint32_t stW = sWu + (c % S) * WSZ * 4;
            #pragma unroll
            for (int ks = 0; ks < 2; ks++) {
                uint32_t af[2][4], bf[2][4];
                #pragma unroll
                for (int tm = 0; tm < 2; tm++)
                    ldsm4(af[tm], stX + (mbase + tm * 16 + rowA) * (LDW * 4)
                                  + ks * 32 + abyte);
                #pragma unroll
                for (int p = 0; p < 2; p++)
                    ldsm4(bf[p], stW + (nbase + p * 16 + rowB) * (LDW * 4)
                                  + ks * 32 + bbyte);
                #pragma unroll
                for (int tm = 0; tm < 2; tm++)
                    #pragma unroll
                    for (int p = 0; p < 2; p++) {
                        mma_bf16(acc[tm][2 * p],     af[tm], bf[p] + 0);
                        mma_bf16(acc[tm][2 * p + 1], af[tm], bf[p] + 2);
                    }
            }
        }

        // epilogue: relu + bias -> sH (bank-conflict-free STS)
        #pragma unroll
        for (int tn = 0; tn < 4; tn++) {
            const int ncol = nbase + tn * 8 + 2 * t;
            const float bb0 = __ldg(&b1[n0 + ncol]);
            const float bb1 = __ldg(&b1[n0 + ncol + 1]);
            #pragma unroll
            for (int tm = 0; tm < 2; tm++)
                #pragma unroll
                for (int half = 0; half < 2; half++) {
                    const int rl = mbase + tm * 16 + g + half * 8;
                    float vx = fmaxf(acc[tm][tn][half * 2 + 0] + bb0, 0.f);
                    float vy = fmaxf(acc[tm][tn][half * 2 + 1] + bb1, 0.f);
                    sH[rl * LDH + n0 / 2 + wn * 16 + tn * 4 + t] =
                        pack_bf16(vx, vy);
                }
        }
        __syncthreads();   // sH + stage buffers coherent before next n-tile
    }

    // stash b2 / w3 into the now-free sX region
    sb2[tid]       = b2[tid];
    sb2[256 + tid] = b2[256 + tid];
    #pragma unroll
    for (int j = 0; j < 4; j++) sw3[j * 256 + tid] = w3[j * 256 + tid];

    // ============ PHASE 2: h2 n-tiles (K=512, A from smem) -> logits =======
    float s[2][2][2] = {};   // [tm][half][class]

    for (int nt = 0; nt < 4; nt++) {
        const int n0 = nt * 128;
        float acc[2][4][4] = {};

        loadW(W2, HID, n0, 0); cp_commit();
        loadW(W2, HID, n0, 1); cp_commit();

        for (int c = 0; c < 16; c++) {
            cp_wait<1>();
            __syncthreads();
            if (c + 2 < 16) loadW(W2, HID, n0, c + 2);
            cp_commit();

            const uint32_t stW = sWu + (c % S) * WSZ * 4;
            #pragma unroll
            for (int ks = 0; ks < 2; ks++) {
                uint32_t af[2][4], bf[2][4];
                #pragma unroll
                for (int tm = 0; tm < 2; tm++)
                    ldsm4(af[tm], sHu + (mbase + tm * 16 + rowA) * (LDH * 4)
                                  + c * 64 + ks * 32 + abyte);
                #pragma unroll
                for (int p = 0; p < 2; p++)
                    ldsm4(bf[p], stW + (nbase + p * 16 + rowB) * (LDW * 4)
                                  + ks * 32 + bbyte);
                #pragma unroll
                for (int tm = 0; tm < 2; tm++)
                    #pragma unroll
                    for (int p = 0; p < 2; p++) {
                        mma_bf16(acc[tm][2 * p],     af[tm], bf[p] + 0);
                        mma_bf16(acc[tm][2 * p + 1], af[tm], bf[p] + 2);
                    }
            }
        }

        // fold relu(h2)+b2 with w3 into logit partials
        #pragma unroll
        for (int tm = 0; tm < 2; tm++)
            #pragma unroll
            for (int half = 0; half < 2; half++)
                #pragma unroll
                for (int tn = 0; tn < 4; tn++) {
                    const int gc = n0 + nbase + tn * 8 + 2 * t;
                    float v0 = fmaxf(acc[tm][tn][half * 2 + 0] + sb2[gc],     0.f);
                    float v1 = fmaxf(acc[tm][tn][half * 2 + 1] + sb2[gc + 1], 0.f);
                    s[tm][half][0] = fmaf(v0, sw3[gc],
                                     fmaf(v1, sw3[gc + 1], s[tm][half][0]));
                    s[tm][half][1] = fmaf(v0, sw3[512 + gc],
                                     fmaf(v1, sw3[512 + gc + 1], s[tm][half][1]));
                }
        __syncthreads();   // stage buffers before next n-tile prologue
    }

    // quad-reduce (t lanes share a row) and cross-warp reduce via sred
    #pragma unroll
    for (int tm = 0; tm < 2; tm++)
        #pragma unroll
        for (int half = 0; half < 2; half++) {
            float s0 = s[tm][half][0], s1 = s[tm][half][1];
            s0 += __shfl_xor_sync(0xffffffffu, s0, 1);
            s0 += __shfl_xor_sync(0xffffffffu, s0, 2);
            s1 += __shfl_xor_sync(0xffffffffu, s1, 1);
            s1 += __shfl_xor_sync(0xffffffffu, s1, 2);
            if (t == 0) {
                const int rl = mbase + tm * 16 + g + half * 8;
                sred[rl * 8 + wn * 2 + 0] = s0;
                sred[rl * 8 + wn * 2 + 1] = s1;
            }
        }
    __syncthreads();

    if (tid < BM) {
        const int row = m0 + tid;
        float s0 = 0.f, s1 = 0.f;
        #pragma unroll
        for (int p = 0; p < 4; p++) {
            s0 += sred[tid * 8 + p * 2 + 0];
            s1 += sred[tid * 8 + p * 2 + 1];
        }
        float l0 = g_fm[row * 2 + 0] + __ldg(&b3[0]) + s0;
        float l1 = g_fm[row * 2 + 1] + __ldg(&b3[1]) + s1;
        float m  = fmaxf(l0, l1);
        float e0 = expf(l0 - m), e1 = expf(l1 - m);
        float inv = 1.0f / (e0 + e1);
        out[row * 2 + 0] = e0 * inv;
        out[row * 2 + 1] = e1 * inv;
    }
}

// ---------------------------------------------------------------------------
// Embeddings + FM (1st + 2nd order) -> g_xh[:, 0:320], g_fm
// ---------------------------------------------------------------------------
__global__ void embed_fm_kernel(
    const int* __restrict__ uid, const int* __restrict__ hour,
    const float* __restrict__ scale,
    const int* __restrict__ gender, const int* __restrict__ age,
    const int* __restrict__ attr,
    const float* __restrict__ user_emb, const float* __restrict__ hour_emb,
    const float* __restrict__ gender_emb, const float* __restrict__ age_emb,
    const float* __restrict__ attr_emb,
    const float* __restrict__ fm_w, const float* __restrict__ fm_b)
{
    int s = threadIdx.x >> 6;
    int k = threadIdx.x & 63;
    int b = blockIdx.x * 4 + s;

    int u  = uid[b];
    int h  = hour[b];
    int g  = gender[b];
    int a  = age[b];
    int at = attr[b];
    float sc = scale[b];

    float e0 = user_emb[(size_t)u * 64 + k];
    float e1 = hour_emb[h * 64 + k];
    float e2 = sc * tanhf(gender_emb[g * 64 + k]);
    float e3 = sc * tanhf(attr_emb[at * 64 + k]);
    float e4 = sc * tanhf(age_emb[a * 64 + k]);

    __nv_bfloat16* xb = g_xh + (size_t)b * 384;
    xb[      k] = __float2bfloat16_rn(e0);
    xb[ 64 + k] = __float2bfloat16_rn(e1);
    xb[128 + k] = __float2bfloat16_rn(e2);
    xb[192 + k] = __float2bfloat16_rn(e3);
    xb[256 + k] = __float2bfloat16_rn(e4);

    float su = e0 + e1 + e2 + e3 + e4;
    float sq = e0*e0 + e1*e1 + e2*e2 + e3*e3 + e4*e4;
    float so = su * su - sq;

    #pragma unroll
    for (int o = 16; o > 0; o >>= 1)
        so += __shfl_down_sync(0xffffffffu, so, o);

    __shared__ float red[4][2];
    if ((k & 31) == 0) red[s][k >> 5] = so;
    __syncthreads();

    if (k == 0) {
        float second = 0.5f * (red[s][0] + red[s][1]);
        long c0 = u;
        long c1 = NUSERS + h;
        long c2 = NUSERS + 24 + g;
        long c3 = NUSERS + 26 + a;
        long c4 = NUSERS + 34 + at;
        #pragma unroll
        for (int j = 0; j < 2; j++) {
            const float* w = fm_w + (size_t)j * VOCAB;
            g_fm[b * 2 + j] =
                w[c0] + w[c1] + w[c2] + w[c3] + w[c4] + fm_b[j] + second;
        }
    }
}

// ---------------------------------------------------------------------------
extern "C" void kernel_launch(void* const* d_in, const int* in_sizes, int n_in,
                              void* d_out, int out_size)
{
    const int*   uid        = (const int*)  d_in[0];
    const int*   hour       = (const int*)  d_in[1];
    const float* visual     = (const float*)d_in[2];
    const float* scale      = (const float*)d_in[3];
    const int*   gender     = (const int*)  d_in[4];
    const int*   age        = (const int*)  d_in[5];
    const int*   attribute  = (const int*)  d_in[6];
    const float* user_emb   = (const float*)d_in[7];
    const float* hour_emb   = (const float*)d_in[8];
    const float* gender_emb = (const float*)d_in[9];
    const float* age_emb    = (const float*)d_in[10];
    const float* attr_emb   = (const float*)d_in[11];
    const float* visu_w     = (const float*)d_in[12];
    const float* visu_b     = (const float*)d_in[13];
    const float* fm_w       = (const float*)d_in[14];
    const float* fm_b       = (const float*)d_in[15];
    const float* w1         = (const float*)d_in[16];
    const float* b1         = (const float*)d_in[17];
    const float* w2         = (const float*)d_in[18];
    const float* b2         = (const float*)d_in[19];
    const float* w3         = (const float*)d_in[20];
    const float* b3         = (const float*)d_in[21];
    float* out = (float*)d_out;

    __nv_bfloat16 *xhp, *w1p, *w2p;
    cudaGetSymbolAddress((void**)&xhp, g_xh);
    cudaGetSymbolAddress((void**)&w1p, g_w1h);
    cudaGetSymbolAddress((void**)&w2p, g_w2h);

    const int SM_VIS = 4 * (64 + 64) * 36 * 4;                 // 73,728 B
    const int SM_FUS = (3 * 1280 + 3 * 2560 + 64 * 260) * 4;   // 112,640 B
    cudaFuncSetAttribute(gemm_tf32_vis, cudaFuncAttributeMaxDynamicSharedMemorySize, SM_VIS);
    cudaFuncSetAttribute(fused_mlp,     cudaFuncAttributeMaxDynamicSharedMemorySize, SM_FUS);

    // fork two side branches off the capture stream
    cudaStream_t s1, s2;
    cudaStreamCreateWithFlags(&s1, cudaStreamNonBlocking);
    cudaStreamCreateWithFlags(&s2, cudaStreamNonBlocking);
    cudaEvent_t ev0, ev1, ev2;
    cudaEventCreateWithFlags(&ev0, cudaEventDisableTiming);
    cudaEventCreateWithFlags(&ev1, cudaEventDisableTiming);
    cudaEventCreateWithFlags(&ev2, cudaEventDisableTiming);

    cudaEventRecord(ev0, 0);
    cudaStreamWaitEvent(s1, ev0, 0);
    cudaStreamWaitEvent(s2, ev0, 0);

    // branch 1 (s1): vis = visual @ visu_w^T + visu_b -> bf16 x[:,320:384]
    gemm_tf32_vis<<<BATCH / 64, 256, SM_VIS, s1>>>(visual, visu_w, visu_b, xhp);

    // branch 2 (s2): weight conversion
    conv_w_kernel<<<448, 256, 0, s2>>>(w1, w2);

    // main stream: embeddings + FM
    embed_fm_kernel<<<BATCH / 4, 256>>>(uid, hour, scale, gender, age, attribute,
                                        user_emb, hour_emb, gender_emb, age_emb,
                                        attr_emb, fm_w, fm_b);

    cudaEventRecord(ev1, s1);
    cudaEventRecord(ev2, s2);
    cudaStreamWaitEvent(0, ev1, 0);
    cudaStreamWaitEvent(0, ev2, 0);

    // fused MLP: h1 (smem) -> h2 (regs) -> logits -> softmax -> out
    fused_mlp<<<BATCH / 64, 256, SM_FUS>>>(xhp, w1p, b1, w2p, b2, w3, b3, out);

    cudaEventDestroy(ev0);
    cudaEventDestroy(ev1);
    cudaEventDestroy(ev2);
    cudaStreamDestroy(s1);
    cudaStreamDestroy(s2);
}